// round 16
// baseline (speedup 1.0000x reference)
#include <cuda_runtime.h>
#include <cooperative_groups.h>

namespace cg = cooperative_groups;

#define NANCH 25200
#define BATCH 8
#define NEGF  (-1e9f)
#define TPB   256
#define NWARP 8

// ord(NEGF) = ~bits(-1e9f)
#define ORDNEG 0x319194D7u
// ord(-5e8f) : validity threshold (score > NEG*0.5)
#define ORDVAL 0x321194D7u
#define FULLM  0xFFFFFFFFu

typedef unsigned int u32;
typedef unsigned long long u64;

// Scratch (static __device__ — no allocation allowed)
__device__ float4 g_box[BATCH * NANCH];
__device__ float  g_area[BATCH * NANCH];
__device__ float  g_score[BATCH * NANCH];

// ---------------------------------------------------------------------------
// Stage 1: class argmax, score mask, box/area gather. Also zero-fills d_out.
// ---------------------------------------------------------------------------
__global__ void prep_kernel(const float* __restrict__ b20, const float* __restrict__ p20, const float* __restrict__ c20,
                            const float* __restrict__ b40, const float* __restrict__ p40, const float* __restrict__ c40,
                            const float* __restrict__ b80, const float* __restrict__ p80, const float* __restrict__ c80,
                            float* __restrict__ out, int out_size)
{
    int gid = blockIdx.x * blockDim.x + threadIdx.x;
    if (gid < out_size) out[gid] = 0.0f;
    if (gid >= BATCH * NANCH) return;

    int b = gid / NANCH;
    int j = gid - b * NANCH;

    const float *bb, *pp, *cc;
    int off;
    if (j < 1200)      { bb = b20; pp = p20; cc = c20; off = b * 1200  + j; }
    else if (j < 6000) { bb = b40; pp = p40; cc = c40; off = b * 4800  + (j - 1200); }
    else               { bb = b80; pp = p80; cc = c80; off = b * 19200 + (j - 6000); }

    float4 box = reinterpret_cast<const float4*>(bb)[off];
    const float4* crow = reinterpret_cast<const float4*>(cc) + off * 20;

    float best = __int_as_float(0xff800000); // -inf
    int bi = 0;
    #pragma unroll
    for (int q = 0; q < 20; q++) {
        float4 v = crow[q];
        if (v.x > best) { best = v.x; bi = 4 * q + 0; }
        if (v.y > best) { best = v.y; bi = 4 * q + 1; }
        if (v.z > best) { best = v.z; bi = 4 * q + 2; }
        if (v.w > best) { best = v.w; bi = 4 * q + 3; }
    }
    float p = pp[off];
    float s = __fmul_rn(p, (float)bi);       // score = p * argmax_class (as float)
    s = (s > 0.25f) ? s : NEGF;              // SCORE_THR mask

    g_box[gid]   = box;
    g_area[gid]  = __fmul_rn(__fsub_rn(box.z, box.x), __fsub_rn(box.w, box.y));
    g_score[gid] = s;
}

// Ordered-float bijection (monotonic u32 keys)
__device__ __forceinline__ u32 ford(float f) {
    u32 u = __float_as_uint(f);
    return u ^ ((u32)(((int)u) >> 31) | 0x80000000u);
}
__device__ __forceinline__ float fuord(u32 o) {
    u32 u = (o & 0x80000000u) ? (o ^ 0x80000000u) : ~o;
    return __uint_as_float(u);
}

// -------- cluster smem primitives --------
__device__ __forceinline__ u32 s2u(const void* p) {
    return (u32)__cvta_generic_to_shared(p);
}
__device__ __forceinline__ u32 mapa_(u32 a, u32 r) {
    u32 d;
    asm("mapa.shared::cluster.u32 %0, %1, %2;" : "=r"(d) : "r"(a), "r"(r));
    return d;
}
__device__ __forceinline__ void stc64(u32 a, u64 v) {
    asm volatile("st.shared::cluster.b64 [%0], %1;" :: "r"(a), "l"(v) : "memory");
}
__device__ __forceinline__ void arrive_rc(u32 a) {
    asm volatile("mbarrier.arrive.release.cluster.shared::cluster.b64 _, [%0];"
                 :: "r"(a) : "memory");
}
__device__ __forceinline__ void bar_init(u32 a, u32 n) {
    asm volatile("mbarrier.init.shared.b64 [%0], %1;" :: "r"(a), "r"(n) : "memory");
}
__device__ __forceinline__ void wait_par(u32 a, u32 ph) {
    u32 done;
    asm volatile(
        "{\n\t.reg .pred p;\n\t"
        "mbarrier.try_wait.parity.acquire.cluster.shared::cta.b64 p, [%1], %2;\n\t"
        "selp.b32 %0, 1, 0, p;\n\t}"
        : "=r"(done) : "r"(a), "r"(ph) : "memory");
    if (!done) {
        asm volatile(
            "{\n\t.reg .pred P;\n"
            "W%=:\n\t"
            "mbarrier.try_wait.parity.acquire.cluster.shared::cta.b64 P, [%0], %1, 0x989680;\n\t"
            "@P bra D%=;\n\t"
            "bra W%=;\n"
            "D%=:\n\t}"
            :: "r"(a), "r"(ph) : "memory");
    }
}
__device__ __forceinline__ u64 packf2(float lo, float hi) {
    return ((u64)__float_as_uint(hi) << 32) | __float_as_uint(lo);
}

// ---------------------------------------------------------------------------
// Stage 2: batched NMS, CTA shards with DEPTH-8 shipped lists, virtual-bound
// entries, and round-deferred bulk anchor suppression.
// Per ROUND: warp top-8 via sent-mask rescan (8 REDUX passes) -> smem ->
// warp0 merges 64 -> CTA top-8, ships to all CS peers (one DSMEM hop).
// Central selection runs over NC = 8*CS register candidates PLUS one always-
// alive VIRTUAL entry per CTA (copy of its shipped slot-8 = hidden-anchor
// bound). Winner valid iff some REAL live entry matches the argmax — the
// broadcast ballot doubles as the soundness test (sel==0 -> re-exchange).
// Winners are logged to smem; register-resident score suppression happens in
// ONE bulk pass per round (off the per-winner serial chain).
// ---------------------------------------------------------------------------
template<int CS>
__global__ void __launch_bounds__(TPB, 1)
nms_kernel(float* __restrict__ out, int out_size)
{
    constexpr int PER   = NANCH / CS;
    constexpr int KM    = (PER + TPB - 1) / TPB;
    constexpr int SLOTS = 8;                 // shipped depth per CTA shard
    constexpr int NC    = CS * SLOTS;        // real candidates per round
    constexpr int EL    = NC / 32;           // entries per lane
    constexpr int LPC   = SLOTS / EL;        // lanes covering one CTA
    constexpr int SBOX_BYTES = ((PER * 16 + 127) / 128) * 128;
    constexpr int WS_OFF   = SBOX_BYTES;               // u64[NWARP*SLOTS]
    constexpr int KEY_OFF  = WS_OFF + NWARP * SLOTS * 8;
    constexpr int BLO_OFF  = KEY_OFF + 2 * NC * 8;
    constexpr int BHI_OFF  = BLO_OFF + 2 * NC * 8;
    constexpr int WL_OFF   = BHI_OFF + 2 * NC * 8;     // u64[100*4] winner log
    constexpr int XBAR_OFF = WL_OFF + 100 * 32;

    cg::cluster_group cluster = cg::this_cluster();
    extern __shared__ unsigned char smem[];
    float4* sbox = reinterpret_cast<float4*>(smem);
    u64* ws  = reinterpret_cast<u64*>(smem + WS_OFF);
    u64* KEY = reinterpret_cast<u64*>(smem + KEY_OFF);
    u64* BLO = reinterpret_cast<u64*>(smem + BLO_OFF);
    u64* BHI = reinterpret_cast<u64*>(smem + BHI_OFF);
    u64* WL  = reinterpret_cast<u64*>(smem + WL_OFF);

    const u32 smem_base = s2u(smem);
    const u32 xbar = smem_base + XBAR_OFF;

    const int t    = threadIdx.x;
    const int wid  = t >> 5;
    const int lane = t & 31;
    const int batch = blockIdx.x / CS;
    const int rank  = blockIdx.x % CS;
    const int base  = rank * PER;

    float y1[KM], x1[KM], y2[KM], x2[KM], ar[KM];
    u32 so[KM];

    #pragma unroll
    for (int k = 0; k < KM; k++) {
        int l = k * TPB + t;
        if (l < PER) {
            int g = batch * NANCH + base + l;
            float4 bx = g_box[g];
            y1[k] = bx.x; x1[k] = bx.y; y2[k] = bx.z; x2[k] = bx.w;
            ar[k] = g_area[g];
            so[k] = ford(g_score[g]);
            sbox[l] = bx;
        }
    }

    if (t == 0) {
        bar_init(xbar + 0, CS);
        bar_init(xbar + 8, CS);
    }

    cluster.sync();   // barriers + sbox visible cluster-wide before first sends

    int emitted = 0;
    bool done = false;

    for (int rnd = 0; !done && emitted < 100; ++rnd) {
        const int b = rnd & 1;
        const u32 ph = (rnd >> 1) & 1;
        const int w0 = emitted;   // winners emitted before this round

        // ---- warp top-8 via sent-mask rescan + 8 REDUX passes ----
        u32 sent = 0;
        #pragma unroll
        for (int p = 0; p < SLOTS; p++) {
            u32 lo = 0, lj = 0xFFFFFFFFu; int lk = 0;
            #pragma unroll
            for (int k = 0; k < KM; k++) {
                int l = k * TPB + t;
                if (l < PER && !((sent >> k) & 1u)) {
                    // ascending k + strict '>' == first-index tie-break in-thread
                    if (so[k] > lo) { lo = so[k]; lj = (u32)(base + l); lk = k; }
                }
            }
            u32 mo = __reduce_max_sync(FULLM, lo);
            u32 mi = __reduce_min_sync(FULLM, (lo == mo) ? lj : 0xFFFFFFFFu);
            if (lane == 0) ws[wid * SLOTS + p] = ((u64)mi << 32) | mo;
            if (lo == mo && lj == mi) sent |= 1u << lk;   // unique idx -> one lane
        }
        __syncthreads();

        // ---- warp0: merge 64 warp entries -> CTA top-8, ship to all peers ----
        if (wid == 0) {
            u64 k0 = ws[lane * 2], k1 = ws[lane * 2 + 1];
            u32 ao0 = (u32)k0, aj0 = (u32)(k0 >> 32);
            u32 ao1 = (u32)k1, aj1 = (u32)(k1 >> 32);
            bool av0 = true, av1 = true;
            u32 co[SLOTS], cjj[SLOTS];
            #pragma unroll
            for (int p = 0; p < SLOTS; p++) {
                u32 lo = 0, lj = 0xFFFFFFFFu; int which = -1;
                if (av0) { lo = ao0; lj = aj0; which = 0; }
                if (av1 && (ao1 > lo || (ao1 == lo && aj1 < lj))) { lo = ao1; lj = aj1; which = 1; }
                u32 mo = __reduce_max_sync(FULLM, lo);
                u32 mi = __reduce_min_sync(FULLM, (lo == mo) ? lj : 0xFFFFFFFFu);
                co[p] = mo; cjj[p] = mi;
                if (lo == mo && lj == mi) { if (which == 0) av0 = false; else av1 = false; }
            }
            if (lane < CS) {
                u32 eb = (u32)((b * NC + rank * SLOTS) * 8);
                u32 dk = mapa_(smem_base + (u32)KEY_OFF + eb, (u32)lane);
                u32 dl = mapa_(smem_base + (u32)BLO_OFF + eb, (u32)lane);
                u32 dh = mapa_(smem_base + (u32)BHI_OFF + eb, (u32)lane);
                #pragma unroll
                for (int p = 0; p < SLOTS; p++) {
                    float4 bx = sbox[cjj[p] - base];
                    stc64(dk + p * 8, ((u64)cjj[p] << 32) | co[p]);
                    stc64(dl + p * 8, packf2(bx.x, bx.y));
                    stc64(dh + p * 8, packf2(bx.z, bx.w));
                }
                arrive_rc(mapa_(xbar + b * 8, (u32)lane));
            }
        }

        wait_par(xbar + b * 8, ph);

        // ---- load NC candidates: e = lane*EL + s (lane groups own whole CTAs) ----
        u32 eo[EL], ej[EL];
        float ey1[EL], ex1[EL], ey2[EL], ex2[EL], ea[EL];
        u32 alivem = (1u << EL) - 1u;
        #pragma unroll
        for (int s = 0; s < EL; s++) {
            int e = lane * EL + s;
            u64 kw  = KEY[b * NC + e];
            u64 pl  = BLO[b * NC + e];
            u64 phh = BHI[b * NC + e];
            eo[s] = (u32)kw; ej[s] = (u32)(kw >> 32);
            ey1[s] = __uint_as_float((u32)pl);  ex1[s] = __uint_as_float((u32)(pl >> 32));
            ey2[s] = __uint_as_float((u32)phh); ex2[s] = __uint_as_float((u32)(phh >> 32));
            ea[s] = __fmul_rn(__fsub_rn(ey2[s], ey1[s]), __fsub_rn(ex2[s], ex1[s]));
        }
        // virtual entry = shipped slot-8 of this lane-group's CTA (always alive)
        const bool vhold = (lane % LPC) == (LPC - 1);
        const u32 vo = vhold ? eo[EL - 1] : 0u;
        const u32 vj = vhold ? ej[EL - 1] : 0xFFFFFFFFu;

        // ---- central multi-select (every warp redundantly, all-register) ----
        while (emitted < 100) {
            u32 lo = vo, lj = vj;   // seed with virtual (hidden-anchor bound)
            #pragma unroll
            for (int s = 0; s < EL; s++) {
                if (alivem & (1u << s)) {
                    if ((eo[s] > lo) || (eo[s] == lo && ej[s] < lj)) { lo = eo[s]; lj = ej[s]; }
                }
            }
            u32 mo = __reduce_max_sync(FULLM, lo);
            u32 mi = __reduce_min_sync(FULLM, (lo == mo) ? lj : 0xFFFFFFFFu);

            if (mo <= ORDVAL) { done = true; break; }          // nothing valid left

            // winner must be a REAL live entry; ballot doubles as soundness test
            float by1 = 0, bx1 = 0, by2 = 0, bx2v = 0;
            bool have = false;
            #pragma unroll
            for (int s = 0; s < EL; s++) {
                if ((alivem & (1u << s)) && eo[s] == mo && ej[s] == mi) {
                    by1 = ey1[s]; bx1 = ex1[s]; by2 = ey2[s]; bx2v = ex2[s];
                    have = true;
                }
            }
            u32 sel = __ballot_sync(FULLM, have);
            if (sel == 0) break;    // virtual dominates: hidden anchor may win -> re-exchange

            int sl = __ffs(sel) - 1;
            float wy1 = __shfl_sync(FULLM, by1, sl);
            float wx1 = __shfl_sync(FULLM, bx1, sl);
            float wy2 = __shfl_sync(FULLM, by2, sl);
            float wx2 = __shfl_sync(FULLM, bx2v, sl);
            float warea = __fmul_rn(__fsub_rn(wy2, wy1), __fsub_rn(wx2, wx1));

            if (t == 0) {
                if (rank == 0) {
                    int ob = (batch * 100 + emitted) * 6;
                    if (ob + 5 < out_size) {
                        out[ob + 0] = fminf(fmaxf(wy1, 0.0f), 1.0f);
                        out[ob + 1] = fminf(fmaxf(wx1, 0.0f), 1.0f);
                        out[ob + 2] = fminf(fmaxf(wy2, 0.0f), 1.0f);
                        out[ob + 3] = fminf(fmaxf(wx2, 0.0f), 1.0f);
                        out[ob + 4] = fuord(mo);
                        out[ob + 5] = 0.0f;
                    }
                }
                // winner log for this CTA's bulk suppression
                WL[emitted * 4 + 0] = ((u64)mi << 32) | mo;
                WL[emitted * 4 + 1] = packf2(wy1, wx1);
                WL[emitted * 4 + 2] = packf2(wy2, wx2);
                WL[emitted * 4 + 3] = (u64)__float_as_uint(warea);
            }
            emitted++;

            // kill + suppress candidate entries vs winner (exact semantics)
            #pragma unroll
            for (int s = 0; s < EL; s++) {
                if (alivem & (1u << s)) {
                    bool kill;
                    if (ej[s] == mi) kill = true;
                    else {
                        float ih = fmaxf(__fsub_rn(fminf(wy2, ey2[s]), fmaxf(wy1, ey1[s])), 0.0f);
                        float iw = fmaxf(__fsub_rn(fminf(wx2, ex2[s]), fmaxf(wx1, ex1[s])), 0.0f);
                        float inter = __fmul_rn(ih, iw);
                        float uni   = __fsub_rn(__fadd_rn(warea, ea[s]), inter);
                        float i2  = __fadd_rn(inter, inter);
                        float thr = __fmaf_rn(uni, 2.384185791015625e-7f, uni);
                        bool upos = uni > 0.0f;
                        kill = upos && (i2 >= thr);
                        if (upos && i2 > uni && i2 < thr)      // rare ambiguous band
                            kill = __fdiv_rn(inter, uni) > 0.5f;
                    }
                    if (kill) alivem &= ~(1u << s);
                }
            }
        } // central while

        // ---- bulk suppression of this round's winners over own anchors ----
        if (!done) {                 // 'done' is uniform across the cluster
            __syncthreads();         // WL entries visible to all warps
            for (int w = w0; w < emitted; ++w) {
                u64 kw = WL[w * 4], p1 = WL[w * 4 + 1], p2 = WL[w * 4 + 2];
                float warea = __uint_as_float((u32)WL[w * 4 + 3]);
                u32 miw = (u32)(kw >> 32);
                float wy1 = __uint_as_float((u32)p1);
                float wx1 = __uint_as_float((u32)(p1 >> 32));
                float wy2 = __uint_as_float((u32)p2);
                float wx2 = __uint_as_float((u32)(p2 >> 32));
                int rsel = (int)miw - (base + t);   // == k*TPB iff thread owns winner
                bool need = false;
                #pragma unroll
                for (int k = 0; k < KM; k++) {
                    int l = k * TPB + t;
                    if (l < PER) {
                        float ih = fmaxf(__fsub_rn(fminf(wy2, y2[k]), fmaxf(wy1, y1[k])), 0.0f);
                        float iw = fmaxf(__fsub_rn(fminf(wx2, x2[k]), fmaxf(wx1, x1[k])), 0.0f);
                        float inter = __fmul_rn(ih, iw);
                        float uni   = __fsub_rn(__fadd_rn(warea, ar[k]), inter);
                        float i2  = __fadd_rn(inter, inter);
                        // thr = RN(uni*(1+2^-22)) — strictly above the 0.5+2^-25 midpoint
                        float thr = __fmaf_rn(uni, 2.384185791015625e-7f, uni);
                        bool upos = uni > 0.0f;
                        bool fast_t = upos && (i2 >= thr);
                        need = need || (upos && (i2 > uni) && (i2 < thr));
                        bool supp = fast_t || (rsel == k * TPB);
                        so[k] = supp ? ORDNEG : so[k];
                    }
                }
                if (need) {
                    // exact-division fixup (astronomically rare band)
                    #pragma unroll
                    for (int k = 0; k < KM; k++) {
                        int l = k * TPB + t;
                        if (l < PER) {
                            float ih = fmaxf(__fsub_rn(fminf(wy2, y2[k]), fmaxf(wy1, y1[k])), 0.0f);
                            float iw = fmaxf(__fsub_rn(fminf(wx2, x2[k]), fmaxf(wx1, x1[k])), 0.0f);
                            float inter = __fmul_rn(ih, iw);
                            float uni   = __fsub_rn(__fadd_rn(warea, ar[k]), inter);
                            float i2  = __fadd_rn(inter, inter);
                            float thr = __fmaf_rn(uni, 2.384185791015625e-7f, uni);
                            if (uni > 0.0f && i2 > uni && i2 < thr) {
                                if (__fdiv_rn(inter, uni) > 0.5f) so[k] = ORDNEG;
                            }
                        }
                    }
                }
            }
        }
    } // rounds

    if (rank == 0 && t == 0) {
        int vi = BATCH * 100 * 6 + batch;
        if (vi < out_size) out[vi] = (float)emitted;
    }
    cluster.sync();   // no CTA may exit while peers may still target its DSMEM
}

// smem totals per cluster size
template<int CS> struct SmemTot {
    static constexpr int PER = NANCH / CS;
    static constexpr int NC  = CS * 8;
    static constexpr int v = ((PER * 16 + 127) / 128) * 128
                           + NWARP * 8 * 8          // ws
                           + 3 * (2 * NC * 8)       // KEY/BLO/BHI planes
                           + 100 * 32               // winner log
                           + 16;                    // xbar
};

// ---------------------------------------------------------------------------
extern "C" void kernel_launch(void* const* d_in, const int* in_sizes, int n_in,
                              void* d_out, int out_size)
{
    const float* b20 = (const float*)d_in[0];
    const float* p20 = (const float*)d_in[1];
    const float* c20 = (const float*)d_in[2];
    const float* b40 = (const float*)d_in[3];
    const float* p40 = (const float*)d_in[4];
    const float* c40 = (const float*)d_in[5];
    const float* b80 = (const float*)d_in[6];
    const float* p80 = (const float*)d_in[7];
    const float* c80 = (const float*)d_in[8];
    float* out = (float*)d_out;

    int total = BATCH * NANCH;
    int blocks = (total + TPB - 1) / TPB;
    prep_kernel<<<blocks, TPB>>>(b20, p20, c20, b40, p40, c40, b80, p80, c80, out, out_size);

    // Prefer cluster=16 (non-portable); fall back to 8 if not grantable.
    cudaFuncSetAttribute(nms_kernel<16>, cudaFuncAttributeNonPortableClusterSizeAllowed, 1);
    cudaFuncSetAttribute(nms_kernel<16>, cudaFuncAttributeMaxDynamicSharedMemorySize, SmemTot<16>::v);
    cudaFuncSetAttribute(nms_kernel<8>,  cudaFuncAttributeMaxDynamicSharedMemorySize, SmemTot<8>::v);

    cudaLaunchConfig_t q = {};
    q.gridDim  = dim3(BATCH * 16, 1, 1);
    q.blockDim = dim3(TPB, 1, 1);
    q.dynamicSmemBytes = SmemTot<16>::v;
    q.stream = 0;
    int maxc = 0;
    cudaOccupancyMaxPotentialClusterSize(&maxc, nms_kernel<16>, &q);

    cudaLaunchAttribute at[1];
    at[0].id = cudaLaunchAttributeClusterDimension;

    if (maxc >= 16) {
        cudaLaunchConfig_t cfg = {};
        cfg.gridDim  = dim3(BATCH * 16, 1, 1);
        cfg.blockDim = dim3(TPB, 1, 1);
        cfg.dynamicSmemBytes = SmemTot<16>::v;
        cfg.stream = 0;
        at[0].val.clusterDim = {16, 1, 1};
        cfg.attrs = at; cfg.numAttrs = 1;
        cudaLaunchKernelEx(&cfg, nms_kernel<16>, out, out_size);
    } else {
        cudaLaunchConfig_t cfg = {};
        cfg.gridDim  = dim3(BATCH * 8, 1, 1);
        cfg.blockDim = dim3(TPB, 1, 1);
        cfg.dynamicSmemBytes = SmemTot<8>::v;
        cfg.stream = 0;
        at[0].val.clusterDim = {8, 1, 1};
        cfg.attrs = at; cfg.numAttrs = 1;
        cudaLaunchKernelEx(&cfg, nms_kernel<8>, out, out_size);
    }
}

// round 17
// speedup vs baseline: 1.4069x; 1.4069x over previous
#include <cuda_runtime.h>
#include <cooperative_groups.h>

namespace cg = cooperative_groups;

#define NANCH 25200
#define BATCH 8
#define NEGF  (-1e9f)
#define TPB   256
#define NWARP 8

// ord(NEGF) = ~bits(-1e9f)
#define ORDNEG 0x319194D7u
// ord(-5e8f) : validity threshold (score > NEG*0.5)
#define ORDVAL 0x321194D7u
#define FULLM  0xFFFFFFFFu

typedef unsigned int u32;
typedef unsigned long long u64;

// Scratch (static __device__ — no allocation allowed)
__device__ float4 g_box[BATCH * NANCH];
__device__ float  g_area[BATCH * NANCH];
__device__ float  g_score[BATCH * NANCH];

// ---------------------------------------------------------------------------
// Stage 1: class argmax, score mask, box/area gather. Also zero-fills d_out.
// ---------------------------------------------------------------------------
__global__ void prep_kernel(const float* __restrict__ b20, const float* __restrict__ p20, const float* __restrict__ c20,
                            const float* __restrict__ b40, const float* __restrict__ p40, const float* __restrict__ c40,
                            const float* __restrict__ b80, const float* __restrict__ p80, const float* __restrict__ c80,
                            float* __restrict__ out, int out_size)
{
    int gid = blockIdx.x * blockDim.x + threadIdx.x;
    if (gid < out_size) out[gid] = 0.0f;
    if (gid >= BATCH * NANCH) return;

    int b = gid / NANCH;
    int j = gid - b * NANCH;

    const float *bb, *pp, *cc;
    int off;
    if (j < 1200)      { bb = b20; pp = p20; cc = c20; off = b * 1200  + j; }
    else if (j < 6000) { bb = b40; pp = p40; cc = c40; off = b * 4800  + (j - 1200); }
    else               { bb = b80; pp = p80; cc = c80; off = b * 19200 + (j - 6000); }

    float4 box = reinterpret_cast<const float4*>(bb)[off];
    const float4* crow = reinterpret_cast<const float4*>(cc) + off * 20;

    float best = __int_as_float(0xff800000); // -inf
    int bi = 0;
    #pragma unroll
    for (int q = 0; q < 20; q++) {
        float4 v = crow[q];
        if (v.x > best) { best = v.x; bi = 4 * q + 0; }
        if (v.y > best) { best = v.y; bi = 4 * q + 1; }
        if (v.z > best) { best = v.z; bi = 4 * q + 2; }
        if (v.w > best) { best = v.w; bi = 4 * q + 3; }
    }
    float p = pp[off];
    float s = __fmul_rn(p, (float)bi);       // score = p * argmax_class (as float)
    s = (s > 0.25f) ? s : NEGF;              // SCORE_THR mask

    g_box[gid]   = box;
    g_area[gid]  = __fmul_rn(__fsub_rn(box.z, box.x), __fsub_rn(box.w, box.y));
    g_score[gid] = s;
}

// Ordered-float bijection (monotonic u32 keys)
__device__ __forceinline__ u32 ford(float f) {
    u32 u = __float_as_uint(f);
    return u ^ ((u32)(((int)u) >> 31) | 0x80000000u);
}
__device__ __forceinline__ float fuord(u32 o) {
    u32 u = (o & 0x80000000u) ? (o ^ 0x80000000u) : ~o;
    return __uint_as_float(u);
}

// -------- cluster smem primitives --------
__device__ __forceinline__ u32 s2u(const void* p) {
    return (u32)__cvta_generic_to_shared(p);
}
__device__ __forceinline__ u32 mapa_(u32 a, u32 r) {
    u32 d;
    asm("mapa.shared::cluster.u32 %0, %1, %2;" : "=r"(d) : "r"(a), "r"(r));
    return d;
}
__device__ __forceinline__ void stc64(u32 a, u64 v) {
    asm volatile("st.shared::cluster.b64 [%0], %1;" :: "r"(a), "l"(v) : "memory");
}
__device__ __forceinline__ void arrive_rc(u32 a) {
    asm volatile("mbarrier.arrive.release.cluster.shared::cluster.b64 _, [%0];"
                 :: "r"(a) : "memory");
}
__device__ __forceinline__ void bar_init(u32 a, u32 n) {
    asm volatile("mbarrier.init.shared.b64 [%0], %1;" :: "r"(a), "r"(n) : "memory");
}
__device__ __forceinline__ void wait_par(u32 a, u32 ph) {
    u32 done;
    asm volatile(
        "{\n\t.reg .pred p;\n\t"
        "mbarrier.try_wait.parity.acquire.cluster.shared::cta.b64 p, [%1], %2;\n\t"
        "selp.b32 %0, 1, 0, p;\n\t}"
        : "=r"(done) : "r"(a), "r"(ph) : "memory");
    if (!done) {
        asm volatile(
            "{\n\t.reg .pred P;\n"
            "W%=:\n\t"
            "mbarrier.try_wait.parity.acquire.cluster.shared::cta.b64 P, [%0], %1, 0x989680;\n\t"
            "@P bra D%=;\n\t"
            "bra W%=;\n"
            "D%=:\n\t}"
            :: "r"(a), "r"(ph) : "memory");
    }
}
__device__ __forceinline__ u64 packf2(float lo, float hi) {
    return ((u64)__float_as_uint(hi) << 32) | __float_as_uint(lo);
}

// ---------------------------------------------------------------------------
// Stage 2: batched NMS, CTA-granular shards with DEPTH-4 shipped lists and
// VIRTUAL-BOUND entries. Per ROUND: per-thread top-4 insert -> warp top-4
// (4 REDUX passes) -> smem -> warp0 CTA top-4 (4 REDUX passes) -> ship 4
// sorted entries to all CS peers (one DSMEM hop, barrier count = CS). Every
// warp redundantly selects winners from the NC = 4*CS register candidates
// PLUS one always-alive VIRTUAL entry per CTA (its shipped slot-4 ORIGINAL
// key = hidden-anchor bound). The winner-broadcast ballot doubles as the
// soundness test: sel==0 -> virtual dominates -> re-exchange. First argmax
// of a round is always real (fresh top-4), so every round emits >= 1 winner.
// ---------------------------------------------------------------------------
template<int CS>
__global__ void __launch_bounds__(TPB, 1)
nms_kernel(float* __restrict__ out, int out_size)
{
    constexpr int PER   = NANCH / CS;
    constexpr int KM    = (PER + TPB - 1) / TPB;
    constexpr int SLOTS = 4;                 // shipped depth per CTA shard
    constexpr int NC    = CS * SLOTS;        // candidates per round
    constexpr int EL    = NC / 32;           // entries per lane (16->2, 8->1)
    constexpr int LPC   = SLOTS / EL;        // lanes covering one CTA
    constexpr int SBOX_BYTES = ((PER * 16 + 127) / 128) * 128;
    constexpr int WS_OFF   = SBOX_BYTES;             // u64[NWARP*SLOTS]
    constexpr int KEY_OFF  = WS_OFF + NWARP * SLOTS * 8;
    constexpr int BLO_OFF  = KEY_OFF + 2 * NC * 8;
    constexpr int BHI_OFF  = BLO_OFF + 2 * NC * 8;
    constexpr int XBAR_OFF = BHI_OFF + 2 * NC * 8;

    cg::cluster_group cluster = cg::this_cluster();
    extern __shared__ unsigned char smem[];
    float4* sbox = reinterpret_cast<float4*>(smem);
    u64* ws  = reinterpret_cast<u64*>(smem + WS_OFF);
    u64* KEY = reinterpret_cast<u64*>(smem + KEY_OFF);
    u64* BLO = reinterpret_cast<u64*>(smem + BLO_OFF);
    u64* BHI = reinterpret_cast<u64*>(smem + BHI_OFF);

    const u32 smem_base = s2u(smem);
    const u32 xbar = smem_base + XBAR_OFF;

    const int t    = threadIdx.x;
    const int wid  = t >> 5;
    const int lane = t & 31;
    const int batch = blockIdx.x / CS;
    const int rank  = blockIdx.x % CS;
    const int base  = rank * PER;

    float y1[KM], x1[KM], y2[KM], x2[KM], ar[KM];
    u32 so[KM];

    #pragma unroll
    for (int k = 0; k < KM; k++) {
        int l = k * TPB + t;
        if (l < PER) {
            int g = batch * NANCH + base + l;
            float4 bx = g_box[g];
            y1[k] = bx.x; x1[k] = bx.y; y2[k] = bx.z; x2[k] = bx.w;
            ar[k] = g_area[g];
            so[k] = ford(g_score[g]);
            sbox[l] = bx;
        }
    }

    if (t == 0) {
        bar_init(xbar + 0, CS);
        bar_init(xbar + 8, CS);
    }

    cluster.sync();   // barriers + sbox visible cluster-wide before first sends

    int emitted = 0;
    bool done = false;

    for (int rnd = 0; !done && emitted < 100; ++rnd) {
        const int b = rnd & 1;
        const u32 ph = (rnd >> 1) & 1;

        // ---- per-thread top-4 (sorted desc; ascending scan + strict '>' ==
        //      first-index tie-break, lex order (score, then smaller idx)) ----
        u32 po[SLOTS] = {0, 0, 0, 0};
        u32 pj[SLOTS] = {0xFFFFFFFFu, 0xFFFFFFFFu, 0xFFFFFFFFu, 0xFFFFFFFFu};
        #pragma unroll
        for (int k = 0; k < KM; k++) {
            int l = k * TPB + t;
            if (l < PER) {
                u32 s = so[k], idx = (u32)(base + l);
                if (s > po[0]) {
                    po[3]=po[2]; pj[3]=pj[2]; po[2]=po[1]; pj[2]=pj[1];
                    po[1]=po[0]; pj[1]=pj[0]; po[0]=s; pj[0]=idx;
                } else if (s > po[1]) {
                    po[3]=po[2]; pj[3]=pj[2]; po[2]=po[1]; pj[2]=pj[1];
                    po[1]=s; pj[1]=idx;
                } else if (s > po[2]) {
                    po[3]=po[2]; pj[3]=pj[2]; po[2]=s; pj[2]=idx;
                } else if (s > po[3]) {
                    po[3]=s; pj[3]=idx;
                }
            }
        }

        // ---- warp top-4 via 4 REDUX passes over per-thread sorted lists ----
        #pragma unroll
        for (int p = 0; p < SLOTS; p++) {
            u32 mo = __reduce_max_sync(FULLM, po[0]);
            u32 mi = __reduce_min_sync(FULLM, (po[0] == mo) ? pj[0] : 0xFFFFFFFFu);
            if (lane == 0) ws[wid * SLOTS + p] = ((u64)mi << 32) | mo;
            bool hit = (po[0] == mo) && (pj[0] == mi);
            if (hit) {
                po[0]=po[1]; pj[0]=pj[1]; po[1]=po[2]; pj[1]=pj[2];
                po[2]=po[3]; pj[2]=pj[3]; po[3]=0; pj[3]=0xFFFFFFFFu;
            }
        }
        __syncthreads();

        // ---- warp0: CTA top-4 over NWARP*SLOTS entries, ship to all peers ----
        if (wid == 0) {
            u32 ko = 0, kj = 0xFFFFFFFFu;
            bool av = false;
            if (lane < NWARP * SLOTS) {
                u64 kw = ws[lane];
                ko = (u32)kw; kj = (u32)(kw >> 32);
                av = true;
            }
            u32 co[SLOTS], cj[SLOTS];
            #pragma unroll
            for (int p = 0; p < SLOTS; p++) {
                u32 mo = __reduce_max_sync(FULLM, av ? ko : 0u);
                u32 mi = __reduce_min_sync(FULLM, (av && ko == mo) ? kj : 0xFFFFFFFFu);
                co[p] = mo; cj[p] = mi;
                if (av && ko == mo && kj == mi) av = false;
            }
            // ship 4 sorted entries (keys always real: PER >> SLOTS)
            if (lane < CS) {
                u32 eb = (u32)((b * NC + rank * SLOTS) * 8);
                u32 dk = mapa_(smem_base + (u32)KEY_OFF + eb, (u32)lane);
                u32 dl = mapa_(smem_base + (u32)BLO_OFF + eb, (u32)lane);
                u32 dh = mapa_(smem_base + (u32)BHI_OFF + eb, (u32)lane);
                #pragma unroll
                for (int p = 0; p < SLOTS; p++) {
                    float4 bx = sbox[cj[p] - base];
                    stc64(dk + p * 8, ((u64)cj[p] << 32) | co[p]);
                    stc64(dl + p * 8, packf2(bx.x, bx.y));
                    stc64(dh + p * 8, packf2(bx.z, bx.w));
                }
                arrive_rc(mapa_(xbar + b * 8, (u32)lane));
            }
        }

        wait_par(xbar + b * 8, ph);

        // ---- load NC candidates: e = lane*EL + s (lane groups own whole CTAs) ----
        u32 eo[EL], ej[EL];
        float ey1[EL], ex1[EL], ey2[EL], ex2[EL], ea[EL];
        u32 alivem = (1u << EL) - 1u;
        #pragma unroll
        for (int s = 0; s < EL; s++) {
            int e = lane * EL + s;
            u64 kw  = KEY[b * NC + e];
            u64 pl  = BLO[b * NC + e];
            u64 phh = BHI[b * NC + e];
            eo[s] = (u32)kw; ej[s] = (u32)(kw >> 32);
            ey1[s] = __uint_as_float((u32)pl);  ex1[s] = __uint_as_float((u32)(pl >> 32));
            ey2[s] = __uint_as_float((u32)phh); ex2[s] = __uint_as_float((u32)(phh >> 32));
            ea[s] = __fmul_rn(__fsub_rn(ey2[s], ey1[s]), __fsub_rn(ex2[s], ex1[s]));
        }
        // virtual entry = shipped slot-4 of this lane-group's CTA (always alive,
        // never killed; = upper bound on that CTA's hidden anchors)
        const bool vhold = (lane % LPC) == (LPC - 1);
        const u32 vo = vhold ? eo[EL - 1] : 0u;
        const u32 vj = vhold ? ej[EL - 1] : 0xFFFFFFFFu;

        // ---- central multi-select (every warp redundantly, all-register) ----
        while (emitted < 100) {
            u32 lo = vo, lj = vj;   // seed with virtual (hidden-anchor bound)
            #pragma unroll
            for (int s = 0; s < EL; s++) {
                if (alivem & (1u << s)) {
                    if ((eo[s] > lo) || (eo[s] == lo && ej[s] < lj)) { lo = eo[s]; lj = ej[s]; }
                }
            }
            u32 mo = __reduce_max_sync(FULLM, lo);
            u32 mi = __reduce_min_sync(FULLM, (lo == mo) ? lj : 0xFFFFFFFFu);

            if (mo <= ORDVAL) { done = true; break; }          // nothing valid left

            // winner must be a REAL live entry; ballot doubles as soundness test
            float by1 = 0, bx1 = 0, by2 = 0, bx2v = 0;
            bool have = false;
            #pragma unroll
            for (int s = 0; s < EL; s++) {
                if ((alivem & (1u << s)) && eo[s] == mo && ej[s] == mi) {
                    by1 = ey1[s]; bx1 = ex1[s]; by2 = ey2[s]; bx2v = ex2[s];
                    have = true;
                }
            }
            u32 sel = __ballot_sync(FULLM, have);
            if (sel == 0) break;    // virtual dominates: hidden anchor may win -> re-exchange

            int sl = __ffs(sel) - 1;
            float wy1 = __shfl_sync(FULLM, by1, sl);
            float wx1 = __shfl_sync(FULLM, bx1, sl);
            float wy2 = __shfl_sync(FULLM, by2, sl);
            float wx2 = __shfl_sync(FULLM, bx2v, sl);

            if (rank == 0 && t == 0) {
                int ob = (batch * 100 + emitted) * 6;
                if (ob + 5 < out_size) {
                    out[ob + 0] = fminf(fmaxf(wy1, 0.0f), 1.0f);
                    out[ob + 1] = fminf(fmaxf(wx1, 0.0f), 1.0f);
                    out[ob + 2] = fminf(fmaxf(wy2, 0.0f), 1.0f);
                    out[ob + 3] = fminf(fmaxf(wx2, 0.0f), 1.0f);
                    out[ob + 4] = fuord(mo);
                    out[ob + 5] = 0.0f;
                }
            }
            emitted++;

            float warea = __fmul_rn(__fsub_rn(wy2, wy1), __fsub_rn(wx2, wx1));

            // kill + suppress candidate entries vs winner (exact semantics)
            #pragma unroll
            for (int s = 0; s < EL; s++) {
                if (alivem & (1u << s)) {
                    bool kill;
                    if (ej[s] == mi) kill = true;
                    else {
                        float ih = fmaxf(__fsub_rn(fminf(wy2, ey2[s]), fmaxf(wy1, ey1[s])), 0.0f);
                        float iw = fmaxf(__fsub_rn(fminf(wx2, ex2[s]), fmaxf(wx1, ex1[s])), 0.0f);
                        float inter = __fmul_rn(ih, iw);
                        float uni   = __fsub_rn(__fadd_rn(warea, ea[s]), inter);
                        float i2  = __fadd_rn(inter, inter);
                        float thr = __fmaf_rn(uni, 2.384185791015625e-7f, uni);
                        bool upos = uni > 0.0f;
                        kill = upos && (i2 >= thr);
                        if (upos && i2 > uni && i2 < thr)      // rare ambiguous band
                            kill = __fdiv_rn(inter, uni) > 0.5f;
                    }
                    if (kill) alivem &= ~(1u << s);
                }
            }

            // suppress register-resident scores (own anchors)
            {
                int rsel = (int)mi - (base + t);   // == k*TPB iff thread owns winner
                bool need = false;
                #pragma unroll
                for (int k = 0; k < KM; k++) {
                    int l = k * TPB + t;
                    if (l < PER) {
                        float ih = fmaxf(__fsub_rn(fminf(wy2, y2[k]), fmaxf(wy1, y1[k])), 0.0f);
                        float iw = fmaxf(__fsub_rn(fminf(wx2, x2[k]), fmaxf(wx1, x1[k])), 0.0f);
                        float inter = __fmul_rn(ih, iw);
                        float uni   = __fsub_rn(__fadd_rn(warea, ar[k]), inter);
                        float i2  = __fadd_rn(inter, inter);
                        // thr = RN(uni*(1+2^-22)) — strictly above the 0.5+2^-25 midpoint
                        float thr = __fmaf_rn(uni, 2.384185791015625e-7f, uni);
                        bool upos = uni > 0.0f;
                        bool fast_t = upos && (i2 >= thr);
                        need = need || (upos && (i2 > uni) && (i2 < thr));
                        bool supp = fast_t || (rsel == k * TPB);
                        so[k] = supp ? ORDNEG : so[k];
                    }
                }
                if (need) {
                    // exact-division fixup (astronomically rare band)
                    #pragma unroll
                    for (int k = 0; k < KM; k++) {
                        int l = k * TPB + t;
                        if (l < PER) {
                            float ih = fmaxf(__fsub_rn(fminf(wy2, y2[k]), fmaxf(wy1, y1[k])), 0.0f);
                            float iw = fmaxf(__fsub_rn(fminf(wx2, x2[k]), fmaxf(wx1, x1[k])), 0.0f);
                            float inter = __fmul_rn(ih, iw);
                            float uni   = __fsub_rn(__fadd_rn(warea, ar[k]), inter);
                            float i2  = __fadd_rn(inter, inter);
                            float thr = __fmaf_rn(uni, 2.384185791015625e-7f, uni);
                            if (uni > 0.0f && i2 > uni && i2 < thr) {
                                if (__fdiv_rn(inter, uni) > 0.5f) so[k] = ORDNEG;
                            }
                        }
                    }
                }
            }
        } // central while
    } // rounds

    if (rank == 0 && t == 0) {
        int vi = BATCH * 100 * 6 + batch;
        if (vi < out_size) out[vi] = (float)emitted;
    }
    cluster.sync();   // no CTA may exit while peers may still target its DSMEM
}

// smem totals per cluster size
template<int CS> struct SmemTot {
    static constexpr int PER = NANCH / CS;
    static constexpr int NC  = CS * 4;
    static constexpr int v = ((PER * 16 + 127) / 128) * 128
                           + NWARP * 4 * 8          // ws
                           + 3 * (2 * NC * 8)       // KEY/BLO/BHI planes
                           + 16;                    // xbar
};

// ---------------------------------------------------------------------------
extern "C" void kernel_launch(void* const* d_in, const int* in_sizes, int n_in,
                              void* d_out, int out_size)
{
    const float* b20 = (const float*)d_in[0];
    const float* p20 = (const float*)d_in[1];
    const float* c20 = (const float*)d_in[2];
    const float* b40 = (const float*)d_in[3];
    const float* p40 = (const float*)d_in[4];
    const float* c40 = (const float*)d_in[5];
    const float* b80 = (const float*)d_in[6];
    const float* p80 = (const float*)d_in[7];
    const float* c80 = (const float*)d_in[8];
    float* out = (float*)d_out;

    int total = BATCH * NANCH;
    int blocks = (total + TPB - 1) / TPB;
    prep_kernel<<<blocks, TPB>>>(b20, p20, c20, b40, p40, c40, b80, p80, c80, out, out_size);

    // Prefer cluster=16 (non-portable); fall back to 8 if not grantable.
    cudaFuncSetAttribute(nms_kernel<16>, cudaFuncAttributeNonPortableClusterSizeAllowed, 1);
    cudaFuncSetAttribute(nms_kernel<16>, cudaFuncAttributeMaxDynamicSharedMemorySize, SmemTot<16>::v);
    cudaFuncSetAttribute(nms_kernel<8>,  cudaFuncAttributeMaxDynamicSharedMemorySize, SmemTot<8>::v);

    cudaLaunchConfig_t q = {};
    q.gridDim  = dim3(BATCH * 16, 1, 1);
    q.blockDim = dim3(TPB, 1, 1);
    q.dynamicSmemBytes = SmemTot<16>::v;
    q.stream = 0;
    int maxc = 0;
    cudaOccupancyMaxPotentialClusterSize(&maxc, nms_kernel<16>, &q);

    cudaLaunchAttribute at[1];
    at[0].id = cudaLaunchAttributeClusterDimension;

    if (maxc >= 16) {
        cudaLaunchConfig_t cfg = {};
        cfg.gridDim  = dim3(BATCH * 16, 1, 1);
        cfg.blockDim = dim3(TPB, 1, 1);
        cfg.dynamicSmemBytes = SmemTot<16>::v;
        cfg.stream = 0;
        at[0].val.clusterDim = {16, 1, 1};
        cfg.attrs = at; cfg.numAttrs = 1;
        cudaLaunchKernelEx(&cfg, nms_kernel<16>, out, out_size);
    } else {
        cudaLaunchConfig_t cfg = {};
        cfg.gridDim  = dim3(BATCH * 8, 1, 1);
        cfg.blockDim = dim3(TPB, 1, 1);
        cfg.dynamicSmemBytes = SmemTot<8>::v;
        cfg.stream = 0;
        at[0].val.clusterDim = {8, 1, 1};
        cfg.attrs = at; cfg.numAttrs = 1;
        cudaLaunchKernelEx(&cfg, nms_kernel<8>, out, out_size);
    }
}